// round 1
// baseline (speedup 1.0000x reference)
#include <cuda_runtime.h>
#include <cstddef>

// ---------------------------------------------------------------------------
// DeepSDSphere: 2-stage SRCNN-style pipeline, fp32 baseline.
// Stage 1: x(4,1,90,180) -> up2x -> concat elev0 -> (4,2,180,360)
//          -> disco(2->64,relu) -> conv5x5(64->32,relu) -> conv5x5(32->1)
// Stage 2: same at (360,720), writes d_out (4,1,360,720) fp32.
// ---------------------------------------------------------------------------

#define B_   4
#define F_   64

// scratch layout (floats)
#define SZ_A   (4u*64u*360u*720u)          // disco output   66,355,200
#define SZ_B2  (4u*32u*360u*720u)          // conv2 output   33,177,600
#define SZ_H   (4u*2u*360u*720u)           // concat input    2,073,600
#define SZ_Y1  (4u*180u*360u)              // stage1 result     259,200
#define OFF_A   0u
#define OFF_B2  (OFF_A + SZ_A)
#define OFF_H   (OFF_B2 + SZ_B2)
#define OFF_Y1  (OFF_H + SZ_H)
#define SCRATCH_FLOATS (OFF_Y1 + SZ_Y1)

__device__ float g_scratch[SCRATCH_FLOATS];

// ---------------------------------------------------------------------------
// Kernel 1: bilinear 2x upsample (align_corners=False, half-pixel) + concat.
// in x: (4,1,Hin,Win).  elev: (4,1,2Hin,2Win).  out: (4,2,2Hin,2Win).
// ---------------------------------------------------------------------------
__global__ void upsample_concat_kernel(const float* __restrict__ x,
                                       const float* __restrict__ elev,
                                       float* __restrict__ out,
                                       int Hin, int Win)
{
    int H2 = Hin * 2, W2 = Win * 2;
    int total = B_ * H2 * W2;
    int idx = blockIdx.x * blockDim.x + threadIdx.x;
    if (idx >= total) return;
    int j = idx % W2;
    int t = idx / W2;
    int i = t % H2;
    int b = t / H2;

    float sy = (i + 0.5f) * 0.5f - 0.5f;
    sy = fminf(fmaxf(sy, 0.0f), (float)(Hin - 1));
    int r0 = (int)floorf(sy);
    int r1 = min(r0 + 1, Hin - 1);
    float ty = sy - (float)r0;

    float sx = (j + 0.5f) * 0.5f - 0.5f;
    sx = fminf(fmaxf(sx, 0.0f), (float)(Win - 1));
    int c0 = (int)floorf(sx);
    int c1 = min(c0 + 1, Win - 1);
    float tx = sx - (float)c0;

    const float* xb = x + (size_t)b * Hin * Win;
    float v00 = xb[r0 * Win + c0];
    float v01 = xb[r0 * Win + c1];
    float v10 = xb[r1 * Win + c0];
    float v11 = xb[r1 * Win + c1];
    float left  = v00 * (1.0f - ty) + v10 * ty;
    float right = v01 * (1.0f - ty) + v11 * ty;
    float v = left * (1.0f - tx) + right * tx;

    size_t plane = (size_t)H2 * W2;
    out[((size_t)b * 2 + 0) * plane + (size_t)i * W2 + j] = v;
    out[((size_t)b * 2 + 1) * plane + (size_t)i * W2 + j] =
        elev[(size_t)b * plane + (size_t)i * W2 + j];
}

// ---------------------------------------------------------------------------
// Kernel 2: disco conv (sparse gather conv) + bias + relu.
// h: (4,2,P) flattened. idx: (P,8). val: (9,P,8). w: (64,2,9). bias: (64).
// out: (4,64,P).
// z[b,c,k] = sum_n h[b,c,idx[p,n]] * val[k,p,n]
// y[b,o,p] = relu( bias[o] + sum_{c,k} z[b,c,k]*w[o,c,k] )
// ---------------------------------------------------------------------------
__global__ __launch_bounds__(256)
void disco_kernel(const float* __restrict__ h,
                  const int*   __restrict__ idx,
                  const float* __restrict__ val,
                  const float* __restrict__ w,
                  const float* __restrict__ bias,
                  float* __restrict__ out,
                  int P)
{
    __shared__ float w_s[F_ * 18];
    __shared__ float b_s[F_];
    for (int t = threadIdx.x; t < F_ * 18; t += 256) w_s[t] = w[t];
    if (threadIdx.x < F_) b_s[threadIdx.x] = bias[threadIdx.x];
    __syncthreads();

    int p = blockIdx.x * 256 + threadIdx.x;
    if (p >= P) return;

    int id[8];
    const int4* ip = reinterpret_cast<const int4*>(idx + (size_t)p * 8);
    int4 ia = ip[0], ib = ip[1];
    id[0]=ia.x; id[1]=ia.y; id[2]=ia.z; id[3]=ia.w;
    id[4]=ib.x; id[5]=ib.y; id[6]=ib.z; id[7]=ib.w;

    float v[9][8];
#pragma unroll
    for (int k = 0; k < 9; k++) {
        const float4* vp = reinterpret_cast<const float4*>(val + ((size_t)k * P + p) * 8);
        float4 a = vp[0], c = vp[1];
        v[k][0]=a.x; v[k][1]=a.y; v[k][2]=a.z; v[k][3]=a.w;
        v[k][4]=c.x; v[k][5]=c.y; v[k][6]=c.z; v[k][7]=c.w;
    }

    for (int b = 0; b < B_; b++) {
        const float* h0 = h + (size_t)(b * 2 + 0) * P;
        const float* h1 = h + (size_t)(b * 2 + 1) * P;
        float g0[8], g1[8];
#pragma unroll
        for (int n = 0; n < 8; n++) { g0[n] = h0[id[n]]; g1[n] = h1[id[n]]; }

        float z0[9], z1[9];
#pragma unroll
        for (int k = 0; k < 9; k++) {
            float s0 = 0.0f, s1 = 0.0f;
#pragma unroll
            for (int n = 0; n < 8; n++) {
                s0 = fmaf(g0[n], v[k][n], s0);
                s1 = fmaf(g1[n], v[k][n], s1);
            }
            z0[k] = s0; z1[k] = s1;
        }

        float* ob = out + (size_t)(b * F_) * P + p;
        for (int o = 0; o < F_; o++) {
            const float* wo = &w_s[o * 18];
            float a = b_s[o];
#pragma unroll
            for (int k = 0; k < 9; k++)
                a = fmaf(z0[k], wo[k], fmaf(z1[k], wo[9 + k], a));
            ob[(size_t)o * P] = fmaxf(a, 0.0f);
        }
    }
}

// ---------------------------------------------------------------------------
// Kernel 3: 5x5 SAME conv, IC=64 -> OC=32, bias + relu.
// Tiling: 32x16 output pixels per block, 256 threads.
// Each thread: 4 pixels x 16 output channels (2 oc-groups across threads).
// IC chunked by 8; input tile + weight chunk staged in shared memory.
// ---------------------------------------------------------------------------
__global__ __launch_bounds__(256, 2)
void conv5x5_ic64_oc32_relu(const float* __restrict__ in,
                            const float* __restrict__ w,
                            const float* __restrict__ bias,
                            float* __restrict__ out,
                            int H, int W)
{
    const int TW = 32, TH = 16, ICC = 8, IC = 64, OC = 32;
    __shared__ float in_s[ICC][TH + 4][TW + 4];   // 8*20*36*4 = 23040 B
    __shared__ float w_s[ICC][25][OC];            // 8*25*32*4 = 25600 B

    int b  = blockIdx.z;
    int x0 = blockIdx.x * TW;
    int y0 = blockIdx.y * TH;
    int tid  = threadIdx.x;
    int slot = tid & 127;
    int ocg  = tid >> 7;          // 0 or 1
    int sx   = slot & 31;
    int sy   = slot >> 5;         // 0..3 -> rows sy*4 .. sy*4+3

    float acc[4][16];
#pragma unroll
    for (int i = 0; i < 4; i++)
#pragma unroll
        for (int j = 0; j < 16; j++) acc[i][j] = 0.0f;

    for (int cc = 0; cc < IC; cc += ICC) {
        __syncthreads();
        const float* inb = in + ((size_t)b * IC + cc) * H * W;
        // stage input tile (with 2-halo, zero pad)
        for (int t = tid; t < ICC * (TH + 4) * (TW + 4); t += 256) {
            int ic  = t / ((TH + 4) * (TW + 4));
            int rem = t - ic * (TH + 4) * (TW + 4);
            int r = rem / (TW + 4);
            int c = rem - r * (TW + 4);
            int gy = y0 - 2 + r;
            int gx = x0 - 2 + c;
            float vv = 0.0f;
            if (gy >= 0 && gy < H && gx >= 0 && gx < W)
                vv = inb[(size_t)ic * H * W + (size_t)gy * W + gx];
            in_s[ic][r][c] = vv;
        }
        // stage weight chunk: w global layout (OC, IC, 5, 5)
        for (int t = tid; t < ICC * 25 * OC; t += 256) {
            int oc  = t / (ICC * 25);
            int rem = t - oc * (ICC * 25);
            int ic  = rem / 25;
            int tap = rem - ic * 25;
            w_s[ic][tap][oc] = w[((size_t)oc * IC + cc + ic) * 25 + tap];
        }
        __syncthreads();

#pragma unroll 1
        for (int ic = 0; ic < ICC; ic++) {
#pragma unroll 1
            for (int dy = 0; dy < 5; dy++) {
#pragma unroll
                for (int dx = 0; dx < 5; dx++) {
                    const float4* wrow = reinterpret_cast<const float4*>(
                        &w_s[ic][dy * 5 + dx][ocg * 16]);
                    float4 w0 = wrow[0], w1 = wrow[1], w2 = wrow[2], w3 = wrow[3];
                    float wv[16] = {w0.x,w0.y,w0.z,w0.w, w1.x,w1.y,w1.z,w1.w,
                                    w2.x,w2.y,w2.z,w2.w, w3.x,w3.y,w3.z,w3.w};
#pragma unroll
                    for (int i = 0; i < 4; i++) {
                        float iv = in_s[ic][sy * 4 + i + dy][sx + dx];
#pragma unroll
                        for (int j = 0; j < 16; j++)
                            acc[i][j] = fmaf(iv, wv[j], acc[i][j]);
                    }
                }
            }
        }
    }

#pragma unroll
    for (int i = 0; i < 4; i++) {
        int y = y0 + sy * 4 + i;
        int x = x0 + sx;
        if (y < H && x < W) {
#pragma unroll
            for (int j = 0; j < 16; j++) {
                int oc = ocg * 16 + j;
                float vv = acc[i][j] + bias[oc];
                out[(((size_t)b * OC + oc) * H + y) * W + x] = fmaxf(vv, 0.0f);
            }
        }
    }
}

// ---------------------------------------------------------------------------
// Kernel 4: 5x5 SAME conv, IC=32 -> OC=1, bias, no relu.
// 32x8 pixel tile, 1 pixel per thread, IC chunked by 8.
// ---------------------------------------------------------------------------
__global__ __launch_bounds__(256)
void conv5x5_ic32_oc1(const float* __restrict__ in,
                      const float* __restrict__ w,
                      const float* __restrict__ bias,
                      float* __restrict__ out,
                      int H, int W)
{
    const int TW = 32, TH = 8, ICC = 8, IC = 32;
    __shared__ float in_s[ICC][TH + 4][TW + 4];   // 8*12*36
    __shared__ float w_s[ICC][25];

    int b  = blockIdx.z;
    int x0 = blockIdx.x * TW;
    int y0 = blockIdx.y * TH;
    int tid = threadIdx.x;
    int sx = tid & 31;
    int sy = tid >> 5;            // 0..7

    float acc = 0.0f;
    for (int cc = 0; cc < IC; cc += ICC) {
        __syncthreads();
        const float* inb = in + ((size_t)b * IC + cc) * H * W;
        for (int t = tid; t < ICC * (TH + 4) * (TW + 4); t += 256) {
            int ic  = t / ((TH + 4) * (TW + 4));
            int rem = t - ic * (TH + 4) * (TW + 4);
            int r = rem / (TW + 4);
            int c = rem - r * (TW + 4);
            int gy = y0 - 2 + r;
            int gx = x0 - 2 + c;
            float vv = 0.0f;
            if (gy >= 0 && gy < H && gx >= 0 && gx < W)
                vv = inb[(size_t)ic * H * W + (size_t)gy * W + gx];
            in_s[ic][r][c] = vv;
        }
        for (int t = tid; t < ICC * 25; t += 256)
            w_s[t / 25][t % 25] = w[(size_t)(cc + t / 25) * 25 + (t % 25)];
        __syncthreads();

#pragma unroll 1
        for (int ic = 0; ic < ICC; ic++) {
#pragma unroll
            for (int dy = 0; dy < 5; dy++)
#pragma unroll
                for (int dx = 0; dx < 5; dx++)
                    acc = fmaf(in_s[ic][sy + dy][sx + dx], w_s[ic][dy * 5 + dx], acc);
        }
    }

    int y = y0 + sy, x = x0 + sx;
    if (y < H && x < W)
        out[((size_t)b * H + y) * W + x] = acc + bias[0];
}

// ---------------------------------------------------------------------------
// Orchestration
// ---------------------------------------------------------------------------
extern "C" void kernel_launch(void* const* d_in, const int* in_sizes, int n_in,
                              void* d_out, int out_size)
{
    const float* x        = (const float*)d_in[0];
    const float* elev0    = (const float*)d_in[1];
    const float* elev1    = (const float*)d_in[2];
    const int*   psi_idx1 = (const int*)  d_in[3];
    const float* psi_val1 = (const float*)d_in[4];
    const float* w1       = (const float*)d_in[5];
    const float* b1       = (const float*)d_in[6];
    const float* cw2_1    = (const float*)d_in[7];
    const float* cb2_1    = (const float*)d_in[8];
    const float* cw3_1    = (const float*)d_in[9];
    const float* cb3_1    = (const float*)d_in[10];
    const int*   psi_idx2 = (const int*)  d_in[11];
    const float* psi_val2 = (const float*)d_in[12];
    const float* w2       = (const float*)d_in[13];
    const float* b2       = (const float*)d_in[14];
    const float* cw2_2    = (const float*)d_in[15];
    const float* cb2_2    = (const float*)d_in[16];
    const float* cw3_2    = (const float*)d_in[17];
    const float* cb3_2    = (const float*)d_in[18];
    float* out = (float*)d_out;

    float* scratch = nullptr;
    cudaGetSymbolAddress((void**)&scratch, g_scratch);
    float* bufA  = scratch + OFF_A;    // disco output
    float* bufB2 = scratch + OFF_B2;   // conv2 output
    float* bufH  = scratch + OFF_H;    // concat input
    float* bufY1 = scratch + OFF_Y1;   // stage1 final

    // ---------------- stage 1: 90x180 -> 180x360 ----------------
    {
        const int H = 180, W = 360, P = H * W;
        int total = B_ * H * W;
        upsample_concat_kernel<<<(total + 255) / 256, 256>>>(x, elev0, bufH, 90, 180);
        disco_kernel<<<(P + 255) / 256, 256>>>(bufH, psi_idx1, psi_val1, w1, b1, bufA, P);
        dim3 g2((W + 31) / 32, (H + 15) / 16, B_);
        conv5x5_ic64_oc32_relu<<<g2, 256>>>(bufA, cw2_1, cb2_1, bufB2, H, W);
        dim3 g3((W + 31) / 32, (H + 7) / 8, B_);
        conv5x5_ic32_oc1<<<g3, 256>>>(bufB2, cw3_1, cb3_1, bufY1, H, W);
    }
    // ---------------- stage 2: 180x360 -> 360x720 ----------------
    {
        const int H = 360, W = 720, P = H * W;
        int total = B_ * H * W;
        upsample_concat_kernel<<<(total + 255) / 256, 256>>>(bufY1, elev1, bufH, 180, 360);
        disco_kernel<<<(P + 255) / 256, 256>>>(bufH, psi_idx2, psi_val2, w2, b2, bufA, P);
        dim3 g2((W + 31) / 32, (H + 15) / 16, B_);
        conv5x5_ic64_oc32_relu<<<g2, 256>>>(bufA, cw2_2, cb2_2, bufB2, H, W);
        dim3 g3((W + 31) / 32, (H + 7) / 8, B_);
        conv5x5_ic32_oc1<<<g3, 256>>>(bufB2, cw3_2, cb3_2, out, H, W);
    }
}

// round 2
// speedup vs baseline: 1.0818x; 1.0818x over previous
#include <cuda_runtime.h>
#include <cstddef>

// ---------------------------------------------------------------------------
// DeepSDSphere: 2-stage SRCNN-style pipeline.
// Round 2 change: conv5x5 64->32 inner loop converted to packed fma.rn.f32x2
// (FFMA2, 2 fp32 FMA per issue slot) with output channels packed in pairs.
// ---------------------------------------------------------------------------

#define B_   4
#define F_   64

typedef unsigned long long u64;

__device__ __forceinline__ u64 pack2(float lo, float hi) {
    u64 r;
    asm("mov.b64 %0, {%1, %2};" : "=l"(r) : "f"(lo), "f"(hi));
    return r;
}
__device__ __forceinline__ void fma2(u64& d, u64 a, u64 b) {
    asm("fma.rn.f32x2 %0, %1, %2, %0;" : "+l"(d) : "l"(a), "l"(b));
}
__device__ __forceinline__ float2 unpack2(u64 v) {
    float lo, hi;
    asm("mov.b64 {%0, %1}, %2;" : "=f"(lo), "=f"(hi) : "l"(v));
    return make_float2(lo, hi);
}

// scratch layout (floats)
#define SZ_A   (4u*64u*360u*720u)          // disco output   66,355,200
#define SZ_B2  (4u*32u*360u*720u)          // conv2 output   33,177,600
#define SZ_H   (4u*2u*360u*720u)           // concat input    2,073,600
#define SZ_Y1  (4u*180u*360u)              // stage1 result     259,200
#define OFF_A   0u
#define OFF_B2  (OFF_A + SZ_A)
#define OFF_H   (OFF_B2 + SZ_B2)
#define OFF_Y1  (OFF_H + SZ_H)
#define SCRATCH_FLOATS (OFF_Y1 + SZ_Y1)

__device__ float g_scratch[SCRATCH_FLOATS];

// ---------------------------------------------------------------------------
// Kernel 1: bilinear 2x upsample (half-pixel) + concat.
// ---------------------------------------------------------------------------
__global__ void upsample_concat_kernel(const float* __restrict__ x,
                                       const float* __restrict__ elev,
                                       float* __restrict__ out,
                                       int Hin, int Win)
{
    int H2 = Hin * 2, W2 = Win * 2;
    int total = B_ * H2 * W2;
    int idx = blockIdx.x * blockDim.x + threadIdx.x;
    if (idx >= total) return;
    int j = idx % W2;
    int t = idx / W2;
    int i = t % H2;
    int b = t / H2;

    float sy = (i + 0.5f) * 0.5f - 0.5f;
    sy = fminf(fmaxf(sy, 0.0f), (float)(Hin - 1));
    int r0 = (int)floorf(sy);
    int r1 = min(r0 + 1, Hin - 1);
    float ty = sy - (float)r0;

    float sx = (j + 0.5f) * 0.5f - 0.5f;
    sx = fminf(fmaxf(sx, 0.0f), (float)(Win - 1));
    int c0 = (int)floorf(sx);
    int c1 = min(c0 + 1, Win - 1);
    float tx = sx - (float)c0;

    const float* xb = x + (size_t)b * Hin * Win;
    float v00 = xb[r0 * Win + c0];
    float v01 = xb[r0 * Win + c1];
    float v10 = xb[r1 * Win + c0];
    float v11 = xb[r1 * Win + c1];
    float left  = v00 * (1.0f - ty) + v10 * ty;
    float right = v01 * (1.0f - ty) + v11 * ty;
    float v = left * (1.0f - tx) + right * tx;

    size_t plane = (size_t)H2 * W2;
    out[((size_t)b * 2 + 0) * plane + (size_t)i * W2 + j] = v;
    out[((size_t)b * 2 + 1) * plane + (size_t)i * W2 + j] =
        elev[(size_t)b * plane + (size_t)i * W2 + j];
}

// ---------------------------------------------------------------------------
// Kernel 2: disco conv (sparse gather conv) + bias + relu.
// ---------------------------------------------------------------------------
__global__ __launch_bounds__(256)
void disco_kernel(const float* __restrict__ h,
                  const int*   __restrict__ idx,
                  const float* __restrict__ val,
                  const float* __restrict__ w,
                  const float* __restrict__ bias,
                  float* __restrict__ out,
                  int P)
{
    __shared__ float w_s[F_ * 18];
    __shared__ float b_s[F_];
    for (int t = threadIdx.x; t < F_ * 18; t += 256) w_s[t] = w[t];
    if (threadIdx.x < F_) b_s[threadIdx.x] = bias[threadIdx.x];
    __syncthreads();

    int p = blockIdx.x * 256 + threadIdx.x;
    if (p >= P) return;

    int id[8];
    const int4* ip = reinterpret_cast<const int4*>(idx + (size_t)p * 8);
    int4 ia = ip[0], ib = ip[1];
    id[0]=ia.x; id[1]=ia.y; id[2]=ia.z; id[3]=ia.w;
    id[4]=ib.x; id[5]=ib.y; id[6]=ib.z; id[7]=ib.w;

    float v[9][8];
#pragma unroll
    for (int k = 0; k < 9; k++) {
        const float4* vp = reinterpret_cast<const float4*>(val + ((size_t)k * P + p) * 8);
        float4 a = vp[0], c = vp[1];
        v[k][0]=a.x; v[k][1]=a.y; v[k][2]=a.z; v[k][3]=a.w;
        v[k][4]=c.x; v[k][5]=c.y; v[k][6]=c.z; v[k][7]=c.w;
    }

    for (int b = 0; b < B_; b++) {
        const float* h0 = h + (size_t)(b * 2 + 0) * P;
        const float* h1 = h + (size_t)(b * 2 + 1) * P;
        float g0[8], g1[8];
#pragma unroll
        for (int n = 0; n < 8; n++) { g0[n] = h0[id[n]]; g1[n] = h1[id[n]]; }

        float z0[9], z1[9];
#pragma unroll
        for (int k = 0; k < 9; k++) {
            float s0 = 0.0f, s1 = 0.0f;
#pragma unroll
            for (int n = 0; n < 8; n++) {
                s0 = fmaf(g0[n], v[k][n], s0);
                s1 = fmaf(g1[n], v[k][n], s1);
            }
            z0[k] = s0; z1[k] = s1;
        }

        float* ob = out + (size_t)(b * F_) * P + p;
        for (int o = 0; o < F_; o++) {
            const float* wo = &w_s[o * 18];
            float a = b_s[o];
#pragma unroll
            for (int k = 0; k < 9; k++)
                a = fmaf(z0[k], wo[k], fmaf(z1[k], wo[9 + k], a));
            ob[(size_t)o * P] = fmaxf(a, 0.0f);
        }
    }
}

// ---------------------------------------------------------------------------
// Kernel 3: 5x5 SAME conv, IC=64 -> OC=32, bias + relu.  FFMA2 version.
// 32x16 pixel tile, 256 threads; thread = 4 pixels x 16 oc (8 packed pairs).
// ---------------------------------------------------------------------------
__global__ __launch_bounds__(256, 2)
void conv5x5_ic64_oc32_relu(const float* __restrict__ in,
                            const float* __restrict__ w,
                            const float* __restrict__ bias,
                            float* __restrict__ out,
                            int H, int W)
{
    const int TW = 32, TH = 16, ICC = 8, IC = 64, OC = 32;
    __shared__ __align__(16) float in_s[ICC][TH + 4][TW + 4];   // 23040 B
    __shared__ __align__(16) float w_s[ICC][25][OC];            // 25600 B

    int b  = blockIdx.z;
    int x0 = blockIdx.x * TW;
    int y0 = blockIdx.y * TH;
    int tid  = threadIdx.x;
    int slot = tid & 127;
    int ocg  = tid >> 7;          // 0 or 1
    int sx   = slot & 31;
    int sy   = slot >> 5;         // 0..3 -> rows sy*4 .. sy*4+3

    u64 acc[4][8];
#pragma unroll
    for (int i = 0; i < 4; i++)
#pragma unroll
        for (int j = 0; j < 8; j++) acc[i][j] = 0ull;

    for (int cc = 0; cc < IC; cc += ICC) {
        __syncthreads();
        const float* inb = in + ((size_t)b * IC + cc) * H * W;
        // stage input tile (with 2-halo, zero pad)
        for (int t = tid; t < ICC * (TH + 4) * (TW + 4); t += 256) {
            int ic  = t / ((TH + 4) * (TW + 4));
            int rem = t - ic * (TH + 4) * (TW + 4);
            int r = rem / (TW + 4);
            int c = rem - r * (TW + 4);
            int gy = y0 - 2 + r;
            int gx = x0 - 2 + c;
            float vv = 0.0f;
            if (gy >= 0 && gy < H && gx >= 0 && gx < W)
                vv = inb[(size_t)ic * H * W + (size_t)gy * W + gx];
            in_s[ic][r][c] = vv;
        }
        // stage weight chunk: w global layout (OC, IC, 5, 5)
        for (int t = tid; t < ICC * 25 * OC; t += 256) {
            int oc  = t / (ICC * 25);
            int rem = t - oc * (ICC * 25);
            int ic  = rem / 25;
            int tap = rem - ic * 25;
            w_s[ic][tap][oc] = w[((size_t)oc * IC + cc + ic) * 25 + tap];
        }
        __syncthreads();

#pragma unroll 1
        for (int ic = 0; ic < ICC; ic++) {
#pragma unroll 1
            for (int dy = 0; dy < 5; dy++) {
#pragma unroll
                for (int dx = 0; dx < 5; dx++) {
                    // 16 oc = 8 packed f32x2 weight pairs (broadcast LDS.128)
                    const u64* wrow = reinterpret_cast<const u64*>(
                        &w_s[ic][dy * 5 + dx][ocg * 16]);
                    u64 wv[8];
#pragma unroll
                    for (int j = 0; j < 8; j++) wv[j] = wrow[j];
#pragma unroll
                    for (int i = 0; i < 4; i++) {
                        float iv = in_s[ic][sy * 4 + i + dy][sx + dx];
                        u64 iv2 = pack2(iv, iv);
#pragma unroll
                        for (int j = 0; j < 8; j++)
                            fma2(acc[i][j], iv2, wv[j]);
                    }
                }
            }
        }
    }

#pragma unroll
    for (int i = 0; i < 4; i++) {
        int y = y0 + sy * 4 + i;
        int x = x0 + sx;
        if (y < H && x < W) {
#pragma unroll
            for (int j = 0; j < 8; j++) {
                int oc = ocg * 16 + 2 * j;
                float2 v = unpack2(acc[i][j]);
                float r0 = fmaxf(v.x + bias[oc], 0.0f);
                float r1 = fmaxf(v.y + bias[oc + 1], 0.0f);
                out[(((size_t)b * OC + oc)     * H + y) * W + x] = r0;
                out[(((size_t)b * OC + oc + 1) * H + y) * W + x] = r1;
            }
        }
    }
}

// ---------------------------------------------------------------------------
// Kernel 4: 5x5 SAME conv, IC=32 -> OC=1, bias, no relu.
// ---------------------------------------------------------------------------
__global__ __launch_bounds__(256)
void conv5x5_ic32_oc1(const float* __restrict__ in,
                      const float* __restrict__ w,
                      const float* __restrict__ bias,
                      float* __restrict__ out,
                      int H, int W)
{
    const int TW = 32, TH = 8, ICC = 8, IC = 32;
    __shared__ float in_s[ICC][TH + 4][TW + 4];
    __shared__ float w_s[ICC][25];

    int b  = blockIdx.z;
    int x0 = blockIdx.x * TW;
    int y0 = blockIdx.y * TH;
    int tid = threadIdx.x;
    int sx = tid & 31;
    int sy = tid >> 5;            // 0..7

    float acc = 0.0f;
    for (int cc = 0; cc < IC; cc += ICC) {
        __syncthreads();
        const float* inb = in + ((size_t)b * IC + cc) * H * W;
        for (int t = tid; t < ICC * (TH + 4) * (TW + 4); t += 256) {
            int ic  = t / ((TH + 4) * (TW + 4));
            int rem = t - ic * (TH + 4) * (TW + 4);
            int r = rem / (TW + 4);
            int c = rem - r * (TW + 4);
            int gy = y0 - 2 + r;
            int gx = x0 - 2 + c;
            float vv = 0.0f;
            if (gy >= 0 && gy < H && gx >= 0 && gx < W)
                vv = inb[(size_t)ic * H * W + (size_t)gy * W + gx];
            in_s[ic][r][c] = vv;
        }
        for (int t = tid; t < ICC * 25; t += 256)
            w_s[t / 25][t % 25] = w[(size_t)(cc + t / 25) * 25 + (t % 25)];
        __syncthreads();

#pragma unroll 1
        for (int ic = 0; ic < ICC; ic++) {
#pragma unroll
            for (int dy = 0; dy < 5; dy++)
#pragma unroll
                for (int dx = 0; dx < 5; dx++)
                    acc = fmaf(in_s[ic][sy + dy][sx + dx], w_s[ic][dy * 5 + dx], acc);
        }
    }

    int y = y0 + sy, x = x0 + sx;
    if (y < H && x < W)
        out[((size_t)b * H + y) * W + x] = acc + bias[0];
}

// ---------------------------------------------------------------------------
// Orchestration
// ---------------------------------------------------------------------------
extern "C" void kernel_launch(void* const* d_in, const int* in_sizes, int n_in,
                              void* d_out, int out_size)
{
    const float* x        = (const float*)d_in[0];
    const float* elev0    = (const float*)d_in[1];
    const float* elev1    = (const float*)d_in[2];
    const int*   psi_idx1 = (const int*)  d_in[3];
    const float* psi_val1 = (const float*)d_in[4];
    const float* w1       = (const float*)d_in[5];
    const float* b1       = (const float*)d_in[6];
    const float* cw2_1    = (const float*)d_in[7];
    const float* cb2_1    = (const float*)d_in[8];
    const float* cw3_1    = (const float*)d_in[9];
    const float* cb3_1    = (const float*)d_in[10];
    const int*   psi_idx2 = (const int*)  d_in[11];
    const float* psi_val2 = (const float*)d_in[12];
    const float* w2       = (const float*)d_in[13];
    const float* b2       = (const float*)d_in[14];
    const float* cw2_2    = (const float*)d_in[15];
    const float* cb2_2    = (const float*)d_in[16];
    const float* cw3_2    = (const float*)d_in[17];
    const float* cb3_2    = (const float*)d_in[18];
    float* out = (float*)d_out;

    float* scratch = nullptr;
    cudaGetSymbolAddress((void**)&scratch, g_scratch);
    float* bufA  = scratch + OFF_A;    // disco output
    float* bufB2 = scratch + OFF_B2;   // conv2 output
    float* bufH  = scratch + OFF_H;    // concat input
    float* bufY1 = scratch + OFF_Y1;   // stage1 final

    // ---------------- stage 1: 90x180 -> 180x360 ----------------
    {
        const int H = 180, W = 360, P = H * W;
        int total = B_ * H * W;
        upsample_concat_kernel<<<(total + 255) / 256, 256>>>(x, elev0, bufH, 90, 180);
        disco_kernel<<<(P + 255) / 256, 256>>>(bufH, psi_idx1, psi_val1, w1, b1, bufA, P);
        dim3 g2((W + 31) / 32, (H + 15) / 16, B_);
        conv5x5_ic64_oc32_relu<<<g2, 256>>>(bufA, cw2_1, cb2_1, bufB2, H, W);
        dim3 g3((W + 31) / 32, (H + 7) / 8, B_);
        conv5x5_ic32_oc1<<<g3, 256>>>(bufB2, cw3_1, cb3_1, bufY1, H, W);
    }
    // ---------------- stage 2: 180x360 -> 360x720 ----------------
    {
        const int H = 360, W = 720, P = H * W;
        int total = B_ * H * W;
        upsample_concat_kernel<<<(total + 255) / 256, 256>>>(bufY1, elev1, bufH, 180, 360);
        disco_kernel<<<(P + 255) / 256, 256>>>(bufH, psi_idx2, psi_val2, w2, b2, bufA, P);
        dim3 g2((W + 31) / 32, (H + 15) / 16, B_);
        conv5x5_ic64_oc32_relu<<<g2, 256>>>(bufA, cw2_2, cb2_2, bufB2, H, W);
        dim3 g3((W + 31) / 32, (H + 7) / 8, B_);
        conv5x5_ic32_oc1<<<g3, 256>>>(bufB2, cw3_2, cb3_2, out, H, W);
    }
}

// round 3
// speedup vs baseline: 1.0827x; 1.0009x over previous
#include <cuda_runtime.h>
#include <cstddef>

// ---------------------------------------------------------------------------
// DeepSDSphere: 2-stage SRCNN-style pipeline.
// Round 2 change: conv5x5 64->32 inner loop converted to packed fma.rn.f32x2
// (FFMA2, 2 fp32 FMA per issue slot) with output channels packed in pairs.
// ---------------------------------------------------------------------------

#define B_   4
#define F_   64

typedef unsigned long long u64;

__device__ __forceinline__ u64 pack2(float lo, float hi) {
    u64 r;
    asm("mov.b64 %0, {%1, %2};" : "=l"(r) : "f"(lo), "f"(hi));
    return r;
}
__device__ __forceinline__ void fma2(u64& d, u64 a, u64 b) {
    asm("fma.rn.f32x2 %0, %1, %2, %0;" : "+l"(d) : "l"(a), "l"(b));
}
__device__ __forceinline__ float2 unpack2(u64 v) {
    float lo, hi;
    asm("mov.b64 {%0, %1}, %2;" : "=f"(lo), "=f"(hi) : "l"(v));
    return make_float2(lo, hi);
}

// scratch layout (floats)
#define SZ_A   (4u*64u*360u*720u)          // disco output   66,355,200
#define SZ_B2  (4u*32u*360u*720u)          // conv2 output   33,177,600
#define SZ_H   (4u*2u*360u*720u)           // concat input    2,073,600
#define SZ_Y1  (4u*180u*360u)              // stage1 result     259,200
#define OFF_A   0u
#define OFF_B2  (OFF_A + SZ_A)
#define OFF_H   (OFF_B2 + SZ_B2)
#define OFF_Y1  (OFF_H + SZ_H)
#define SCRATCH_FLOATS (OFF_Y1 + SZ_Y1)

__device__ float g_scratch[SCRATCH_FLOATS];

// ---------------------------------------------------------------------------
// Kernel 1: bilinear 2x upsample (half-pixel) + concat.
// ---------------------------------------------------------------------------
__global__ void upsample_concat_kernel(const float* __restrict__ x,
                                       const float* __restrict__ elev,
                                       float* __restrict__ out,
                                       int Hin, int Win)
{
    int H2 = Hin * 2, W2 = Win * 2;
    int total = B_ * H2 * W2;
    int idx = blockIdx.x * blockDim.x + threadIdx.x;
    if (idx >= total) return;
    int j = idx % W2;
    int t = idx / W2;
    int i = t % H2;
    int b = t / H2;

    float sy = (i + 0.5f) * 0.5f - 0.5f;
    sy = fminf(fmaxf(sy, 0.0f), (float)(Hin - 1));
    int r0 = (int)floorf(sy);
    int r1 = min(r0 + 1, Hin - 1);
    float ty = sy - (float)r0;

    float sx = (j + 0.5f) * 0.5f - 0.5f;
    sx = fminf(fmaxf(sx, 0.0f), (float)(Win - 1));
    int c0 = (int)floorf(sx);
    int c1 = min(c0 + 1, Win - 1);
    float tx = sx - (float)c0;

    const float* xb = x + (size_t)b * Hin * Win;
    float v00 = xb[r0 * Win + c0];
    float v01 = xb[r0 * Win + c1];
    float v10 = xb[r1 * Win + c0];
    float v11 = xb[r1 * Win + c1];
    float left  = v00 * (1.0f - ty) + v10 * ty;
    float right = v01 * (1.0f - ty) + v11 * ty;
    float v = left * (1.0f - tx) + right * tx;

    size_t plane = (size_t)H2 * W2;
    out[((size_t)b * 2 + 0) * plane + (size_t)i * W2 + j] = v;
    out[((size_t)b * 2 + 1) * plane + (size_t)i * W2 + j] =
        elev[(size_t)b * plane + (size_t)i * W2 + j];
}

// ---------------------------------------------------------------------------
// Kernel 2: disco conv (sparse gather conv) + bias + relu.
// ---------------------------------------------------------------------------
__global__ __launch_bounds__(256)
void disco_kernel(const float* __restrict__ h,
                  const int*   __restrict__ idx,
                  const float* __restrict__ val,
                  const float* __restrict__ w,
                  const float* __restrict__ bias,
                  float* __restrict__ out,
                  int P)
{
    __shared__ float w_s[F_ * 18];
    __shared__ float b_s[F_];
    for (int t = threadIdx.x; t < F_ * 18; t += 256) w_s[t] = w[t];
    if (threadIdx.x < F_) b_s[threadIdx.x] = bias[threadIdx.x];
    __syncthreads();

    int p = blockIdx.x * 256 + threadIdx.x;
    if (p >= P) return;

    int id[8];
    const int4* ip = reinterpret_cast<const int4*>(idx + (size_t)p * 8);
    int4 ia = ip[0], ib = ip[1];
    id[0]=ia.x; id[1]=ia.y; id[2]=ia.z; id[3]=ia.w;
    id[4]=ib.x; id[5]=ib.y; id[6]=ib.z; id[7]=ib.w;

    float v[9][8];
#pragma unroll
    for (int k = 0; k < 9; k++) {
        const float4* vp = reinterpret_cast<const float4*>(val + ((size_t)k * P + p) * 8);
        float4 a = vp[0], c = vp[1];
        v[k][0]=a.x; v[k][1]=a.y; v[k][2]=a.z; v[k][3]=a.w;
        v[k][4]=c.x; v[k][5]=c.y; v[k][6]=c.z; v[k][7]=c.w;
    }

    for (int b = 0; b < B_; b++) {
        const float* h0 = h + (size_t)(b * 2 + 0) * P;
        const float* h1 = h + (size_t)(b * 2 + 1) * P;
        float g0[8], g1[8];
#pragma unroll
        for (int n = 0; n < 8; n++) { g0[n] = h0[id[n]]; g1[n] = h1[id[n]]; }

        float z0[9], z1[9];
#pragma unroll
        for (int k = 0; k < 9; k++) {
            float s0 = 0.0f, s1 = 0.0f;
#pragma unroll
            for (int n = 0; n < 8; n++) {
                s0 = fmaf(g0[n], v[k][n], s0);
                s1 = fmaf(g1[n], v[k][n], s1);
            }
            z0[k] = s0; z1[k] = s1;
        }

        float* ob = out + (size_t)(b * F_) * P + p;
        for (int o = 0; o < F_; o++) {
            const float* wo = &w_s[o * 18];
            float a = b_s[o];
#pragma unroll
            for (int k = 0; k < 9; k++)
                a = fmaf(z0[k], wo[k], fmaf(z1[k], wo[9 + k], a));
            ob[(size_t)o * P] = fmaxf(a, 0.0f);
        }
    }
}

// ---------------------------------------------------------------------------
// Kernel 3: 5x5 SAME conv, IC=64 -> OC=32, bias + relu.  FFMA2 version.
// 32x16 pixel tile, 256 threads; thread = 4 pixels x 16 oc (8 packed pairs).
// ---------------------------------------------------------------------------
__global__ __launch_bounds__(256, 2)
void conv5x5_ic64_oc32_relu(const float* __restrict__ in,
                            const float* __restrict__ w,
                            const float* __restrict__ bias,
                            float* __restrict__ out,
                            int H, int W)
{
    const int TW = 32, TH = 16, ICC = 8, IC = 64, OC = 32;
    __shared__ __align__(16) float in_s[ICC][TH + 4][TW + 4];   // 23040 B
    __shared__ __align__(16) float w_s[ICC][25][OC];            // 25600 B

    int b  = blockIdx.z;
    int x0 = blockIdx.x * TW;
    int y0 = blockIdx.y * TH;
    int tid  = threadIdx.x;
    int slot = tid & 127;
    int ocg  = tid >> 7;          // 0 or 1
    int sx   = slot & 31;
    int sy   = slot >> 5;         // 0..3 -> rows sy*4 .. sy*4+3

    u64 acc[4][8];
#pragma unroll
    for (int i = 0; i < 4; i++)
#pragma unroll
        for (int j = 0; j < 8; j++) acc[i][j] = 0ull;

    for (int cc = 0; cc < IC; cc += ICC) {
        __syncthreads();
        const float* inb = in + ((size_t)b * IC + cc) * H * W;
        // stage input tile (with 2-halo, zero pad)
        for (int t = tid; t < ICC * (TH + 4) * (TW + 4); t += 256) {
            int ic  = t / ((TH + 4) * (TW + 4));
            int rem = t - ic * (TH + 4) * (TW + 4);
            int r = rem / (TW + 4);
            int c = rem - r * (TW + 4);
            int gy = y0 - 2 + r;
            int gx = x0 - 2 + c;
            float vv = 0.0f;
            if (gy >= 0 && gy < H && gx >= 0 && gx < W)
                vv = inb[(size_t)ic * H * W + (size_t)gy * W + gx];
            in_s[ic][r][c] = vv;
        }
        // stage weight chunk: w global layout (OC, IC, 5, 5)
        for (int t = tid; t < ICC * 25 * OC; t += 256) {
            int oc  = t / (ICC * 25);
            int rem = t - oc * (ICC * 25);
            int ic  = rem / 25;
            int tap = rem - ic * 25;
            w_s[ic][tap][oc] = w[((size_t)oc * IC + cc + ic) * 25 + tap];
        }
        __syncthreads();

#pragma unroll 1
        for (int ic = 0; ic < ICC; ic++) {
#pragma unroll 1
            for (int dy = 0; dy < 5; dy++) {
#pragma unroll
                for (int dx = 0; dx < 5; dx++) {
                    // 16 oc = 8 packed f32x2 weight pairs (broadcast LDS.128)
                    const u64* wrow = reinterpret_cast<const u64*>(
                        &w_s[ic][dy * 5 + dx][ocg * 16]);
                    u64 wv[8];
#pragma unroll
                    for (int j = 0; j < 8; j++) wv[j] = wrow[j];
#pragma unroll
                    for (int i = 0; i < 4; i++) {
                        float iv = in_s[ic][sy * 4 + i + dy][sx + dx];
                        u64 iv2 = pack2(iv, iv);
#pragma unroll
                        for (int j = 0; j < 8; j++)
                            fma2(acc[i][j], iv2, wv[j]);
                    }
                }
            }
        }
    }

#pragma unroll
    for (int i = 0; i < 4; i++) {
        int y = y0 + sy * 4 + i;
        int x = x0 + sx;
        if (y < H && x < W) {
#pragma unroll
            for (int j = 0; j < 8; j++) {
                int oc = ocg * 16 + 2 * j;
                float2 v = unpack2(acc[i][j]);
                float r0 = fmaxf(v.x + bias[oc], 0.0f);
                float r1 = fmaxf(v.y + bias[oc + 1], 0.0f);
                out[(((size_t)b * OC + oc)     * H + y) * W + x] = r0;
                out[(((size_t)b * OC + oc + 1) * H + y) * W + x] = r1;
            }
        }
    }
}

// ---------------------------------------------------------------------------
// Kernel 4: 5x5 SAME conv, IC=32 -> OC=1, bias, no relu.
// ---------------------------------------------------------------------------
__global__ __launch_bounds__(256)
void conv5x5_ic32_oc1(const float* __restrict__ in,
                      const float* __restrict__ w,
                      const float* __restrict__ bias,
                      float* __restrict__ out,
                      int H, int W)
{
    const int TW = 32, TH = 8, ICC = 8, IC = 32;
    __shared__ float in_s[ICC][TH + 4][TW + 4];
    __shared__ float w_s[ICC][25];

    int b  = blockIdx.z;
    int x0 = blockIdx.x * TW;
    int y0 = blockIdx.y * TH;
    int tid = threadIdx.x;
    int sx = tid & 31;
    int sy = tid >> 5;            // 0..7

    float acc = 0.0f;
    for (int cc = 0; cc < IC; cc += ICC) {
        __syncthreads();
        const float* inb = in + ((size_t)b * IC + cc) * H * W;
        for (int t = tid; t < ICC * (TH + 4) * (TW + 4); t += 256) {
            int ic  = t / ((TH + 4) * (TW + 4));
            int rem = t - ic * (TH + 4) * (TW + 4);
            int r = rem / (TW + 4);
            int c = rem - r * (TW + 4);
            int gy = y0 - 2 + r;
            int gx = x0 - 2 + c;
            float vv = 0.0f;
            if (gy >= 0 && gy < H && gx >= 0 && gx < W)
                vv = inb[(size_t)ic * H * W + (size_t)gy * W + gx];
            in_s[ic][r][c] = vv;
        }
        for (int t = tid; t < ICC * 25; t += 256)
            w_s[t / 25][t % 25] = w[(size_t)(cc + t / 25) * 25 + (t % 25)];
        __syncthreads();

#pragma unroll 1
        for (int ic = 0; ic < ICC; ic++) {
#pragma unroll
            for (int dy = 0; dy < 5; dy++)
#pragma unroll
                for (int dx = 0; dx < 5; dx++)
                    acc = fmaf(in_s[ic][sy + dy][sx + dx], w_s[ic][dy * 5 + dx], acc);
        }
    }

    int y = y0 + sy, x = x0 + sx;
    if (y < H && x < W)
        out[((size_t)b * H + y) * W + x] = acc + bias[0];
}

// ---------------------------------------------------------------------------
// Orchestration
// ---------------------------------------------------------------------------
extern "C" void kernel_launch(void* const* d_in, const int* in_sizes, int n_in,
                              void* d_out, int out_size)
{
    const float* x        = (const float*)d_in[0];
    const float* elev0    = (const float*)d_in[1];
    const float* elev1    = (const float*)d_in[2];
    const int*   psi_idx1 = (const int*)  d_in[3];
    const float* psi_val1 = (const float*)d_in[4];
    const float* w1       = (const float*)d_in[5];
    const float* b1       = (const float*)d_in[6];
    const float* cw2_1    = (const float*)d_in[7];
    const float* cb2_1    = (const float*)d_in[8];
    const float* cw3_1    = (const float*)d_in[9];
    const float* cb3_1    = (const float*)d_in[10];
    const int*   psi_idx2 = (const int*)  d_in[11];
    const float* psi_val2 = (const float*)d_in[12];
    const float* w2       = (const float*)d_in[13];
    const float* b2       = (const float*)d_in[14];
    const float* cw2_2    = (const float*)d_in[15];
    const float* cb2_2    = (const float*)d_in[16];
    const float* cw3_2    = (const float*)d_in[17];
    const float* cb3_2    = (const float*)d_in[18];
    float* out = (float*)d_out;

    float* scratch = nullptr;
    cudaGetSymbolAddress((void**)&scratch, g_scratch);
    float* bufA  = scratch + OFF_A;    // disco output
    float* bufB2 = scratch + OFF_B2;   // conv2 output
    float* bufH  = scratch + OFF_H;    // concat input
    float* bufY1 = scratch + OFF_Y1;   // stage1 final

    // ---------------- stage 1: 90x180 -> 180x360 ----------------
    {
        const int H = 180, W = 360, P = H * W;
        int total = B_ * H * W;
        upsample_concat_kernel<<<(total + 255) / 256, 256>>>(x, elev0, bufH, 90, 180);
        disco_kernel<<<(P + 255) / 256, 256>>>(bufH, psi_idx1, psi_val1, w1, b1, bufA, P);
        dim3 g2((W + 31) / 32, (H + 15) / 16, B_);
        conv5x5_ic64_oc32_relu<<<g2, 256>>>(bufA, cw2_1, cb2_1, bufB2, H, W);
        dim3 g3((W + 31) / 32, (H + 7) / 8, B_);
        conv5x5_ic32_oc1<<<g3, 256>>>(bufB2, cw3_1, cb3_1, bufY1, H, W);
    }
    // ---------------- stage 2: 180x360 -> 360x720 ----------------
    {
        const int H = 360, W = 720, P = H * W;
        int total = B_ * H * W;
        upsample_concat_kernel<<<(total + 255) / 256, 256>>>(bufY1, elev1, bufH, 180, 360);
        disco_kernel<<<(P + 255) / 256, 256>>>(bufH, psi_idx2, psi_val2, w2, b2, bufA, P);
        dim3 g2((W + 31) / 32, (H + 15) / 16, B_);
        conv5x5_ic64_oc32_relu<<<g2, 256>>>(bufA, cw2_2, cb2_2, bufB2, H, W);
        dim3 g3((W + 31) / 32, (H + 7) / 8, B_);
        conv5x5_ic32_oc1<<<g3, 256>>>(bufB2, cw3_2, cb3_2, out, H, W);
    }
}